// round 15
// baseline (speedup 1.0000x reference)
#include <cuda_runtime.h>
#include <math.h>
#include <stdint.h>

typedef unsigned long long ull;

#define S_    128
#define Bz    32
#define DIN   256
#define DBERT 768
#define H_    512
#define D0_   1024
#define NDJ   4096
#define NTP   32
#define NTM   64

// ---------------- persistent device scratch ----------------
__device__ float d_preG [(size_t)NDJ * 4096];    // layer-0 pre-activations [dj][t*B+b]
__device__ float d_preG1[(size_t)NDJ * 4096];    // layer-1 pre-activations (written during lstm0)
__device__ float d_out0T[(size_t)1024 * 4096];   // [2H][S*B]
__device__ float d_out1T[(size_t)1024 * 4096];   // [2H][S*B]
__device__ float d_hbuf[2][2][512][32];          // [parity][dir][hidx][b]
__device__ float d_bertbias[NDJ * Bz];           // [dj][b]
__device__ float d_feat[(size_t)S_ * Bz * 96];   // [S*B][96]
__device__ volatile unsigned d_bcnt[4];          // monotonic arrival counters

__device__ __forceinline__ float fsig(float x) { return 1.f / (1.f + __expf(-x)); }
__device__ __forceinline__ float ftanh(float x) { return 2.f / (1.f + __expf(-2.f * x)) - 1.f; }
__device__ __forceinline__ void fma2(ull& d, ull a, ull b) {
    asm("fma.rn.f32x2 %0, %1, %2, %0;" : "+l"(d) : "l"(a), "l"(b));
}
__device__ __forceinline__ ull packdup(float v) {
    ull r; asm("mov.b64 %0, {%1,%1};" : "=l"(r) : "f"(v)); return r;
}
__device__ __forceinline__ float2 unpackf2(ull v) {
    float2 r; asm("mov.b64 {%0,%1}, %2;" : "=f"(r.x), "=f"(r.y) : "l"(v)); return r;
}
__device__ __forceinline__ unsigned ld_acq32(const volatile unsigned* p) {
    unsigned v;
    asm volatile("ld.acquire.gpu.global.u32 %0, [%1];" : "=r"(v) : "l"((const unsigned*)p) : "memory");
    return v;
}
__device__ __forceinline__ void pdl_wait() {
    asm volatile("griddepcontrol.wait;" ::: "memory");
}
__device__ __forceinline__ void pdl_launch_dependents() {
    asm volatile("griddepcontrol.launch_dependents;" ::: "memory");
}

// ---------------- bert bias: bias0[dj][b]  (+ inlined zero of barrier state/out) ----------------
#define BB_SMEM (32 * 772 * 4)
__global__ __launch_bounds__(256) void bert_bias_kernel(
    const float* __restrict__ bert, const float* __restrict__ w_ih0,
    const float* __restrict__ b_ih0, const float* __restrict__ b_hh0,
    float* out)
{
    extern __shared__ float sh[];   // bert_sh[32][772]
    const int tid = threadIdx.x;
    if (blockIdx.x == 0) {
        if (tid < 4) d_bcnt[tid] = 0u;
        if (tid == 0) out[0] = 0.f;
    }
    for (int idx = tid; idx < Bz * DBERT / 4; idx += 256) {
        float4 v = ((const float4*)bert)[idx];
        int e = idx * 4;
        int b = e / DBERT, k = e % DBERT;
        *(float4*)&sh[b * 772 + k] = v;
    }
    __syncthreads();
    const int djl = tid & 63, bq = tid >> 6;
    const int dj = blockIdx.x * 64 + djl;
    const float* wrow = w_ih0 + (size_t)dj * D0_ + DIN;
    float acc[8];
#pragma unroll
    for (int i = 0; i < 8; i++) acc[i] = 0.f;
    for (int k = 0; k < DBERT; k += 4) {
        float4 w4 = *(const float4*)&wrow[k];
#pragma unroll
        for (int i = 0; i < 8; i++) {
            int b = bq * 8 + i;
            float4 h4 = *(const float4*)&sh[b * 772 + k];
            acc[i] += w4.x * h4.x + w4.y * h4.y + w4.z * h4.z + w4.w * h4.w;
        }
    }
    float bias = b_ih0[dj] + b_hh0[dj];
#pragma unroll
    for (int i = 0; i < 8; i++)
        d_bertbias[(size_t)dj * 32 + bq * 8 + i] = acc[i] + bias;
}

// ---------------- GEMM: dst[m=dj][n=t*B+b] = A[m]·B[n] (+bias) ----------------
// 128x128 tile, 256 threads, double-buffered smem (A undup; dup in regs). 2 blocks/SM.
// WAIT=1: dst=d_preG1, mid-out n-order, PDL wait + acquire-spin on layer-0 counters.
#define GEMM_SMEM ((2 * 16 * 132 + 2 * 16 * 132) * 4)
template<int BT, int WAIT>
__global__ __launch_bounds__(256, 2) void gemm_kernel(
    const float* __restrict__ A, int lda, int K,
    const float* __restrict__ Bp, int ldb,
    int use_bb, const float* __restrict__ b1, const float* __restrict__ b2)
{
    extern __shared__ float sh[];
    float* AsBase = sh;                  // [2][16][132]
    float* WsBase = sh + 2 * 16 * 132;   // [2][16][132]
    const float* Bx = Bp ? Bp : (const float*)d_out0T;
    float* dstG = WAIT ? d_preG1 : d_preG;
    const int tid = threadIdx.x;

    int nt;
    if (WAIT) {
        pdl_wait();
        int j = blockIdx.x >> 1;
        nt = (blockIdx.x & 1) ? (16 + j) : (15 - j);   // readiness (mid-out) order
        if (tid == 0) {
            unsigned tf = 64u * (unsigned)(4 * nt + 4);       // fwd: t<=4nt+3 done
            unsigned tb = 64u * (unsigned)(128 - 4 * nt);     // bwd: t>=4nt done
            while (ld_acq32(&d_bcnt[0]) < tf) __nanosleep(256);
            while (ld_acq32(&d_bcnt[1]) < tb) __nanosleep(256);
        }
        __syncthreads();
    } else {
        nt = blockIdx.x;
    }
    const int m0 = blockIdx.y * 128, n0 = nt * 128;

    const int am = tid >> 1, ak = (tid & 1) * 8;
    const int bk = tid >> 4, bn = (tid & 15) * 8;
    const int cn = tid >> 1, ck = (tid & 1) * 8;
    const int ty = tid >> 4, tx = tid & 15;

    ull acc[8][4];
#pragma unroll
    for (int i = 0; i < 8; i++)
#pragma unroll
        for (int j = 0; j < 4; j++) acc[i][j] = 0ull;

    float4 ra0, ra1, rb0, rb1;
    const int NT = K / 16;

    {
        const float* ap = &A[(size_t)(m0 + am) * lda + ak];
        ra0 = *(const float4*)ap; ra1 = *(const float4*)(ap + 4);
        if (BT) {
            const float* bp = &Bx[(size_t)bk * ldb + n0 + bn];
            rb0 = *(const float4*)bp; rb1 = *(const float4*)(bp + 4);
        } else {
            const float* bp = &Bx[(size_t)(n0 + cn) * ldb + ck];
            rb0 = *(const float4*)bp; rb1 = *(const float4*)(bp + 4);
        }
    }

    int p = 0;
    {
        float* As = AsBase;
        float* Ws = WsBase;
        float av[8] = {ra0.x, ra0.y, ra0.z, ra0.w, ra1.x, ra1.y, ra1.z, ra1.w};
#pragma unroll
        for (int i = 0; i < 8; i++) As[(ak + i) * 132 + am] = av[i];
        if (BT) {
            *(float4*)&Ws[bk * 132 + bn] = rb0;
            *(float4*)&Ws[bk * 132 + bn + 4] = rb1;
        } else {
            float bv[8] = {rb0.x, rb0.y, rb0.z, rb0.w, rb1.x, rb1.y, rb1.z, rb1.w};
#pragma unroll
            for (int i = 0; i < 8; i++) Ws[(ck + i) * 132 + cn] = bv[i];
        }
    }
    __syncthreads();

    for (int kt = 0; kt < NT; kt++) {
        if (kt + 1 < NT) {
            int k0 = (kt + 1) * 16;
            const float* ap = &A[(size_t)(m0 + am) * lda + k0 + ak];
            ra0 = *(const float4*)ap; ra1 = *(const float4*)(ap + 4);
            if (BT) {
                const float* bp = &Bx[(size_t)(k0 + bk) * ldb + n0 + bn];
                rb0 = *(const float4*)bp; rb1 = *(const float4*)(bp + 4);
            } else {
                const float* bp = &Bx[(size_t)(n0 + cn) * ldb + k0 + ck];
                rb0 = *(const float4*)bp; rb1 = *(const float4*)(bp + 4);
            }
        }
        {
            const float* As = AsBase + p * (16 * 132);
            const float* Ws = WsBase + p * (16 * 132);
#pragma unroll
            for (int kk = 0; kk < 16; kk++) {
                const float* ap = &As[kk * 132 + ty * 8];
                float4 f0 = *(const float4*)ap;
                float4 f1 = *(const float4*)(ap + 4);
                ull ax0 = packdup(f0.x), ax1 = packdup(f0.y);
                ull ax2 = packdup(f0.z), ax3 = packdup(f0.w);
                ull ax4 = packdup(f1.x), ax5 = packdup(f1.y);
                ull ax6 = packdup(f1.z), ax7 = packdup(f1.w);
                const float* wp = &Ws[kk * 132 + tx * 8];
                ulonglong2 w01 = *(const ulonglong2*)(wp);
                ulonglong2 w23 = *(const ulonglong2*)(wp + 4);
                fma2(acc[0][0], ax0, w01.x); fma2(acc[0][1], ax0, w01.y);
                fma2(acc[0][2], ax0, w23.x); fma2(acc[0][3], ax0, w23.y);
                fma2(acc[1][0], ax1, w01.x); fma2(acc[1][1], ax1, w01.y);
                fma2(acc[1][2], ax1, w23.x); fma2(acc[1][3], ax1, w23.y);
                fma2(acc[2][0], ax2, w01.x); fma2(acc[2][1], ax2, w01.y);
                fma2(acc[2][2], ax2, w23.x); fma2(acc[2][3], ax2, w23.y);
                fma2(acc[3][0], ax3, w01.x); fma2(acc[3][1], ax3, w01.y);
                fma2(acc[3][2], ax3, w23.x); fma2(acc[3][3], ax3, w23.y);
                fma2(acc[4][0], ax4, w01.x); fma2(acc[4][1], ax4, w01.y);
                fma2(acc[4][2], ax4, w23.x); fma2(acc[4][3], ax4, w23.y);
                fma2(acc[5][0], ax5, w01.x); fma2(acc[5][1], ax5, w01.y);
                fma2(acc[5][2], ax5, w23.x); fma2(acc[5][3], ax5, w23.y);
                fma2(acc[6][0], ax6, w01.x); fma2(acc[6][1], ax6, w01.y);
                fma2(acc[6][2], ax6, w23.x); fma2(acc[6][3], ax6, w23.y);
                fma2(acc[7][0], ax7, w01.x); fma2(acc[7][1], ax7, w01.y);
                fma2(acc[7][2], ax7, w23.x); fma2(acc[7][3], ax7, w23.y);
            }
        }
        if (kt + 1 < NT) {
            float* As = AsBase + (p ^ 1) * (16 * 132);
            float* Ws = WsBase + (p ^ 1) * (16 * 132);
            float av[8] = {ra0.x, ra0.y, ra0.z, ra0.w, ra1.x, ra1.y, ra1.z, ra1.w};
#pragma unroll
            for (int i = 0; i < 8; i++) As[(ak + i) * 132 + am] = av[i];
            if (BT) {
                *(float4*)&Ws[bk * 132 + bn] = rb0;
                *(float4*)&Ws[bk * 132 + bn + 4] = rb1;
            } else {
                float bv[8] = {rb0.x, rb0.y, rb0.z, rb0.w, rb1.x, rb1.y, rb1.z, rb1.w};
#pragma unroll
                for (int i = 0; i < 8; i++) Ws[(ck + i) * 132 + cn] = bv[i];
            }
        }
        __syncthreads();
        p ^= 1;
    }

#pragma unroll
    for (int i = 0; i < 8; i++) {
        int m = m0 + ty * 8 + i;
        float rowbias = use_bb ? 0.f : (b1[m] + b2[m]);
        float4 o0, o1;
        float2 v0 = unpackf2(acc[i][0]);
        float2 v1 = unpackf2(acc[i][1]);
        float2 v2 = unpackf2(acc[i][2]);
        float2 v3 = unpackf2(acc[i][3]);
        o0 = make_float4(v0.x, v0.y, v1.x, v1.y);
        o1 = make_float4(v2.x, v2.y, v3.x, v3.y);
        if (use_bb) {
            int bb = (tx * 8) & 31;
            float4 c0 = *(const float4*)&d_bertbias[(size_t)m * 32 + bb];
            float4 c1 = *(const float4*)&d_bertbias[(size_t)m * 32 + bb + 4];
            o0.x += c0.x; o0.y += c0.y; o0.z += c0.z; o0.w += c0.w;
            o1.x += c1.x; o1.y += c1.y; o1.z += c1.z; o1.w += c1.w;
        } else {
            o0.x += rowbias; o0.y += rowbias; o0.z += rowbias; o0.w += rowbias;
            o1.x += rowbias; o1.y += rowbias; o1.z += rowbias; o1.w += rowbias;
        }
        float* dst = &dstG[(size_t)m * 4096 + n0 + tx * 8];
        *(float4*)dst = o0;
        *(float4*)(dst + 4) = o1;
    }
}

// ---------------- persistent BiLSTM layer kernel (512 threads, 8-way k-split) ----------------
#define PSMEM ((512 * 32 + 512 * 32 + 8 * 32 * 33) * 4)
__global__ __launch_bounds__(512) void lstm_layer_kernel(
    const float* __restrict__ whh, int layer)
{
    extern __shared__ float sh[];
    float* wS  = sh;                         // [512][32] W rows, UNduplicated
    float* hT  = sh + 512 * 32;              // [512][32]
    float* red = sh + 512 * 32 + 512 * 32;   // [8][32][33]

    const int tid = threadIdx.x;
    const int d = blockIdx.x >> 6;
    const int hch = blockIdx.x & 63;
    const int hbase = hch * 8;
    const int bslot = layer * 2 + d;
    float* outT = layer ? d_out1T : d_out0T;
    const float* preG = layer ? d_preG1 : d_preG;

    // load 32 W_hh rows: wS[k*32 + c] = W[dj(c)][k]
    {
        int c = tid >> 4, kc = tid & 15;
        int g = c >> 3, hh = c & 7;
        const float* wrow = whh + ((size_t)d * 2048 + g * 512 + hbase + hh) * 512;
        for (int k = kc * 32; k < kc * 32 + 32; k += 4) {
            float4 v = *(const float4*)&wrow[k];
            wS[(k + 0) * 32 + c] = v.x;
            wS[(k + 1) * 32 + c] = v.y;
            wS[(k + 2) * 32 + c] = v.z;
            wS[(k + 3) * 32 + c] = v.w;
        }
    }
    __syncthreads();

    // allow PDL-dependent kernel (overlapped gemm/heads) to begin launching
    pdl_launch_dependents();

    const int ks = tid >> 6, b8 = (tid >> 3) & 7, c8 = tid & 7;   // ks in [0,8)
    const int cu_hh = tid >> 5, cu_b = tid & 31;                  // valid tid<256
    float c_reg = 0.f;

    for (int ti = 0; ti < S_; ti++) {
        const int t = d ? (S_ - 1 - ti) : ti;

        // prefetch gate pre-activations (tid < 256; hidden under gate GEMM)
        float pg[4];
        if (tid < 256) {
#pragma unroll
            for (int gi = 0; gi < 4; gi++) {
                size_t dj = (size_t)d * 2048 + (size_t)gi * 512 + hbase + cu_hh;
                pg[gi] = __ldcg(&preG[dj * 4096 + t * 32 + cu_b]);
            }
        }

        if (ti > 0) {
            // ---- gate GEMM over k in [ks*64, ks*64+64), reg double-buffered ----
            ull acc[4][2];
#pragma unroll
            for (int i = 0; i < 4; i++) { acc[i][0] = 0ull; acc[i][1] = 0ull; }

            const float* wk = wS + c8 * 4 + ks * 64 * 32;
            const float* hk = hT + b8 * 4 + ks * 64 * 32;
            float4 nw = *(const float4*)wk;
            ulonglong2 nh = *(const ulonglong2*)hk;
            wk += 32; hk += 32;
#pragma unroll 4
            for (int k = 0; k < 63; k++) {
                float4 w4 = nw; ulonglong2 hv = nh;
                nw = *(const float4*)wk;
                nh = *(const ulonglong2*)hk;
                wk += 32; hk += 32;
                ull wx0 = packdup(w4.x);
                ull wx1 = packdup(w4.y);
                ull wx2 = packdup(w4.z);
                ull wx3 = packdup(w4.w);
                fma2(acc[0][0], hv.x, wx0); fma2(acc[0][1], hv.y, wx0);
                fma2(acc[1][0], hv.x, wx1); fma2(acc[1][1], hv.y, wx1);
                fma2(acc[2][0], hv.x, wx2); fma2(acc[2][1], hv.y, wx2);
                fma2(acc[3][0], hv.x, wx3); fma2(acc[3][1], hv.y, wx3);
            }
            {
                ull wx0 = packdup(nw.x);
                ull wx1 = packdup(nw.y);
                ull wx2 = packdup(nw.z);
                ull wx3 = packdup(nw.w);
                fma2(acc[0][0], nh.x, wx0); fma2(acc[0][1], nh.y, wx0);
                fma2(acc[1][0], nh.x, wx1); fma2(acc[1][1], nh.y, wx1);
                fma2(acc[2][0], nh.x, wx2); fma2(acc[2][1], nh.y, wx2);
                fma2(acc[3][0], nh.x, wx3); fma2(acc[3][1], nh.y, wx3);
            }

            // write partials: red[ks][b][c]
            {
                float* rp = red + ks * 1056 + (b8 * 4) * 33 + c8 * 4;
#pragma unroll
                for (int cc = 0; cc < 4; cc++) {
#pragma unroll
                    for (int bp = 0; bp < 2; bp++) {
                        float2 v = unpackf2(acc[cc][bp]);
                        rp[(2 * bp + 0) * 33 + cc] = v.x;
                        rp[(2 * bp + 1) * 33 + cc] = v.y;
                    }
                }
            }
            __syncthreads();
        }

        // ---- cell update: tid < 256, thread (cu_b, cu_hh) ----
        if (tid < 256) {
            float g[4];
#pragma unroll
            for (int gi = 0; gi < 4; gi++) {
                float s = pg[gi];
                if (ti > 0) {
                    int c = gi * 8 + cu_hh;
#pragma unroll
                    for (int kk = 0; kk < 8; kk++)
                        s += red[kk * 1056 + cu_b * 33 + c];
                }
                g[gi] = s;
            }
            float cn = fsig(g[1]) * c_reg + fsig(g[0]) * ftanh(g[2]);
            float hn = fsig(g[3]) * ftanh(cn);
            c_reg = cn;
            int hidx = hbase + cu_hh;
            d_hbuf[ti & 1][d][hidx][cu_b] = hn;
            outT[((size_t)(d * 512 + hidx)) * 4096 + t * 32 + cu_b] = hn;
        }

        // ---- per-direction grid barrier: monotonic arrival counter ----
        __syncthreads();
        if (tid == 0) {
            __threadfence();
            unsigned target = 64u * (unsigned)(ti + 1);
            unsigned old = atomicAdd((unsigned*)&d_bcnt[bslot], 1u);
            if (old + 1u < target) {
                while (d_bcnt[bslot] < target) { }
            }
            __threadfence();
        }
        __syncthreads();

        // ---- stage next h into SMEM (contiguous d_hbuf, 512 threads) ----
        if (ti < S_ - 1) {
            const float4* s4 = (const float4*)&d_hbuf[ti & 1][d][0][0];
            float4* d4 = (float4*)hT;
            for (int i = tid; i < 512 * 32 / 4; i += 512) d4[i] = __ldcg(&s4[i]);
            __syncthreads();
        }
    }
}

// ---------------- heads: d_feat from d_out1T; WAIT=1 overlaps lstm1 via counters ----------------
template<int WAIT>
__global__ __launch_bounds__(256) void head_kernel(
    const float* __restrict__ wp, const float* __restrict__ bp,
    const float* __restrict__ wm, const float* __restrict__ bm)
{
    __shared__ float Ash[32][65];
    __shared__ float Wsh[64][100];
    const int tid = threadIdx.x;

    int tblk;
    if (WAIT) {
        pdl_wait();
        int j = blockIdx.x >> 1;
        tblk = (blockIdx.x & 1) ? (64 + j) : (63 - j);   // readiness (mid-out) order
        if (tid == 0) {
            unsigned tf = 64u * (unsigned)(tblk + 1);     // fwd wrote t=tblk
            unsigned tb = 64u * (unsigned)(128 - tblk);   // bwd wrote t=tblk
            while (ld_acq32(&d_bcnt[2]) < tf) __nanosleep(256);
            while (ld_acq32(&d_bcnt[3]) < tb) __nanosleep(256);
        }
        __syncthreads();
    } else {
        tblk = blockIdx.x;
    }
    const int row0 = tblk * 32;
    const int r = tid >> 3, jq = tid & 7;
    float acc[12];
#pragma unroll
    for (int j = 0; j < 12; j++) acc[j] = 0.f;

    const float* Xt = (const float*)d_out1T;
    for (int k0 = 0; k0 < 1024; k0 += 64) {
        for (int idx = tid; idx < 32 * 64; idx += 256) {
            int kk = idx >> 5, rr = idx & 31;
            Ash[rr][kk] = Xt[(size_t)(k0 + kk) * 4096 + row0 + rr];
        }
        for (int idx = tid; idx < 96 * 64; idx += 256) {
            int j = idx >> 6, kk = idx & 63;
            float v = (j < 32) ? wp[(size_t)j * 1024 + k0 + kk]
                               : wm[(size_t)(j - 32) * 1024 + k0 + kk];
            Wsh[kk][j] = v;
        }
        __syncthreads();
        for (int k = 0; k < 64; k++) {
            float a = Ash[r][k];
#pragma unroll
            for (int j = 0; j < 12; j++) acc[j] += a * Wsh[k][jq * 12 + j];
        }
        __syncthreads();
    }
#pragma unroll
    for (int j = 0; j < 12; j++) {
        int jj = jq * 12 + j;
        float bias = (jj < 32) ? bp[jj] : bm[jj - 32];
        d_feat[(size_t)(row0 + r) * 96 + jj] = acc[j] + bias;
    }
}

// ---------------- CRF ----------------
template <int K>
__global__ __launch_bounds__(128) void crf_kernel(
    int off, const int* __restrict__ labels,
    const float* __restrict__ start, const float* __restrict__ trans,
    const float* __restrict__ endv, float* __restrict__ out)
{
    __shared__ float tr[K * K];
    __shared__ float al[2][K];
    __shared__ float red[128];
    const int b = blockIdx.x, tid = threadIdx.x;

    for (int i = tid; i < K * K; i += 128) tr[i] = trans[i];

    float local = 0.f;
    for (int t = tid; t < S_; t += 128)
        local += d_feat[((size_t)t * Bz + b) * 96 + off + labels[t * Bz + b]];
    for (int t = tid; t < S_ - 1; t += 128)
        local += trans[labels[t * Bz + b] * K + labels[(t + 1) * Bz + b]];
    red[tid] = local;
    __syncthreads();
    for (int s = 64; s > 0; s >>= 1) {
        if (tid < s) red[tid] += red[tid + s];
        __syncthreads();
    }

    if (tid < K) al[0][tid] = start[tid] + d_feat[((size_t)0 * Bz + b) * 96 + off + tid];
    __syncthreads();
    int cur = 0;
    for (int t = 1; t < S_; t++) {
        if (tid < K) {
            float m = -1e30f;
#pragma unroll 4
            for (int i = 0; i < K; i++) {
                float v = al[cur][i] + tr[i * K + tid];
                m = fmaxf(m, v);
            }
            float s = 0.f;
#pragma unroll 4
            for (int i = 0; i < K; i++)
                s += __expf(al[cur][i] + tr[i * K + tid] - m);
            al[cur ^ 1][tid] = m + __logf(s) + d_feat[((size_t)t * Bz + b) * 96 + off + tid];
        }
        __syncthreads();
        cur ^= 1;
    }
    if (tid == 0) {
        float m = -1e30f;
        for (int j = 0; j < K; j++) m = fmaxf(m, al[cur][j] + endv[j]);
        float s = 0.f;
        for (int j = 0; j < K; j++) s += __expf(al[cur][j] + endv[j] - m);
        float den = m + __logf(s);
        float num = red[0] + start[labels[b]] + endv[labels[(S_ - 1) * Bz + b]];
        atomicAdd(out, -(num - den));
    }
}

// ---------------- launch ----------------
extern "C" void kernel_launch(void* const* d_in, const int* in_sizes, int n_in,
                              void* d_out, int out_size)
{
    const float* src  = (const float*)d_in[0];
    const float* bert = (const float*)d_in[1];
    const int*   labp = (const int*)d_in[2];
    const int*   labm = (const int*)d_in[3];
    const float* w_ih = (const float*)d_in[4];
    const float* w_hh = (const float*)d_in[5];
    const float* b_ih = (const float*)d_in[6];
    const float* b_hh = (const float*)d_in[7];
    const float* hwp  = (const float*)d_in[8];
    const float* hbp  = (const float*)d_in[9];
    const float* hwm  = (const float*)d_in[10];
    const float* hbm  = (const float*)d_in[11];
    const float* st_p = (const float*)d_in[12];
    const float* en_p = (const float*)d_in[13];
    const float* tr_p = (const float*)d_in[14];
    const float* st_m = (const float*)d_in[15];
    const float* en_m = (const float*)d_in[16];
    const float* tr_m = (const float*)d_in[17];
    float* out = (float*)d_out;

    cudaFuncSetAttribute(lstm_layer_kernel, cudaFuncAttributeMaxDynamicSharedMemorySize, PSMEM);
    cudaFuncSetAttribute(bert_bias_kernel, cudaFuncAttributeMaxDynamicSharedMemorySize, BB_SMEM);
    cudaFuncSetAttribute((const void*)gemm_kernel<0,0>, cudaFuncAttributeMaxDynamicSharedMemorySize, GEMM_SMEM);
    cudaFuncSetAttribute((const void*)gemm_kernel<1,1>, cudaFuncAttributeMaxDynamicSharedMemorySize, GEMM_SMEM);

    dim3 g128(32, 32);

    // 0: bert bias (also zeroes barrier counters + out)
    bert_bias_kernel<<<64, 256, BB_SMEM>>>(bert, w_ih, b_ih, b_hh, out);
    // 1: layer-0 input GEMM (K=256, bert folded into bias) -> d_preG
    gemm_kernel<0,0><<<g128, 256, GEMM_SMEM>>>(w_ih, 1024, 256, src, 256, 1, nullptr, nullptr);
    // 2: layer-0 BiLSTM (signals dependents after W-load)
    lstm_layer_kernel<<<128, 512, PSMEM>>>(w_hh, 0);
    // 3: layer-1 input GEMM -> d_preG1, PDL-overlapped with lstm0
    {
        cudaLaunchConfig_t cfg = {};
        cfg.gridDim = g128;
        cfg.blockDim = dim3(256, 1, 1);
        cfg.dynamicSmemBytes = GEMM_SMEM;
        cfg.stream = 0;
        cudaLaunchAttribute attr[1];
        attr[0].id = cudaLaunchAttributeProgrammaticStreamSerialization;
        attr[0].val.programmaticStreamSerializationAllowed = 1;
        cfg.attrs = attr;
        cfg.numAttrs = 1;
        cudaError_t e = cudaLaunchKernelEx(&cfg, gemm_kernel<1,1>,
            (const float*)(w_ih + (size_t)4096 * 1024), 1024, 1024,
            (const float*)nullptr, 4096, 0,
            (const float*)(b_ih + 4096), (const float*)(b_hh + 4096));
        if (e != cudaSuccess) {
            cudaGetLastError();
            gemm_kernel<1,1><<<g128, 256, GEMM_SMEM>>>(w_ih + (size_t)4096 * 1024, 1024, 1024,
                                                       nullptr, 4096, 0, b_ih + 4096, b_hh + 4096);
        }
    }
    // 4: layer-1 BiLSTM
    lstm_layer_kernel<<<128, 512, PSMEM>>>(w_hh + (size_t)2 * 2048 * 512, 1);
    // 5: heads, PDL-overlapped with lstm1 (per-t spin on counters 2,3)
    {
        cudaLaunchConfig_t cfg = {};
        cfg.gridDim = dim3(128, 1, 1);
        cfg.blockDim = dim3(256, 1, 1);
        cfg.dynamicSmemBytes = 0;
        cfg.stream = 0;
        cudaLaunchAttribute attr[1];
        attr[0].id = cudaLaunchAttributeProgrammaticStreamSerialization;
        attr[0].val.programmaticStreamSerializationAllowed = 1;
        cfg.attrs = attr;
        cfg.numAttrs = 1;
        cudaError_t e = cudaLaunchKernelEx(&cfg, head_kernel<1>, hwp, hbp, hwm, hbm);
        if (e != cudaSuccess) {
            cudaGetLastError();
            head_kernel<1><<<128, 256>>>(hwp, hbp, hwm, hbm);
        }
    }
    // 6-7: CRFs (stream-ordered after heads)
    crf_kernel<NTP><<<32, 128>>>(0, labp, st_p, tr_p, en_p, out);
    crf_kernel<NTM><<<32, 128>>>(32, labm, st_m, tr_m, en_m, out);
}

// round 16
// speedup vs baseline: 1.7713x; 1.7713x over previous
#include <cuda_runtime.h>
#include <math.h>
#include <stdint.h>

typedef unsigned long long ull;

#define S_    128
#define Bz    32
#define DIN   256
#define DBERT 768
#define H_    512
#define D0_   1024
#define NDJ   4096
#define NTP   32
#define NTM   64

// ---------------- persistent device scratch ----------------
__device__ float d_preG [(size_t)NDJ * 4096];    // layer-0 pre-activations [dj][t*B+b]
__device__ float d_preG1[(size_t)NDJ * 4096];    // layer-1 pre-activations (written during lstm0)
__device__ float d_out0T[(size_t)1024 * 4096];   // [2H][S*B]
__device__ float d_out1T[(size_t)1024 * 4096];   // [2H][S*B]
__device__ float d_hbuf[2][2][512][32];          // [parity][dir][hidx][b]
__device__ float d_bertbias[NDJ * Bz];           // [dj][b]
__device__ float d_feat[(size_t)S_ * Bz * 96];   // [S*B][96]
__device__ volatile unsigned d_bcnt[4][32];      // monotonic counters, 128B apart

__device__ __forceinline__ float fsig(float x) { return 1.f / (1.f + __expf(-x)); }
__device__ __forceinline__ float ftanh(float x) { return 2.f / (1.f + __expf(-2.f * x)) - 1.f; }
__device__ __forceinline__ void fma2(ull& d, ull a, ull b) {
    asm("fma.rn.f32x2 %0, %1, %2, %0;" : "+l"(d) : "l"(a), "l"(b));
}
__device__ __forceinline__ ull packdup(float v) {
    ull r; asm("mov.b64 %0, {%1,%1};" : "=l"(r) : "f"(v)); return r;
}
__device__ __forceinline__ float2 unpackf2(ull v) {
    float2 r; asm("mov.b64 {%0,%1}, %2;" : "=f"(r.x), "=f"(r.y) : "l"(v)); return r;
}
__device__ __forceinline__ unsigned ld_acq32(const volatile unsigned* p) {
    unsigned v;
    asm volatile("ld.acquire.gpu.global.u32 %0, [%1];" : "=r"(v) : "l"((const unsigned*)p) : "memory");
    return v;
}
__device__ __forceinline__ void pdl_launch_dependents() {
    asm volatile("griddepcontrol.launch_dependents;" ::: "memory");
}

// ---------------- bert bias: bias0[dj][b]  (+ inlined zero of barrier state/out) ----------------
#define BB_SMEM (32 * 772 * 4)
__global__ __launch_bounds__(256) void bert_bias_kernel(
    const float* __restrict__ bert, const float* __restrict__ w_ih0,
    const float* __restrict__ b_ih0, const float* __restrict__ b_hh0,
    float* out)
{
    extern __shared__ float sh[];   // bert_sh[32][772]
    const int tid = threadIdx.x;
    if (blockIdx.x == 0) {
        if (tid < 4) d_bcnt[tid][0] = 0u;
        if (tid == 0) out[0] = 0.f;
    }
    for (int idx = tid; idx < Bz * DBERT / 4; idx += 256) {
        float4 v = ((const float4*)bert)[idx];
        int e = idx * 4;
        int b = e / DBERT, k = e % DBERT;
        *(float4*)&sh[b * 772 + k] = v;
    }
    __syncthreads();
    const int djl = tid & 63, bq = tid >> 6;
    const int dj = blockIdx.x * 64 + djl;
    const float* wrow = w_ih0 + (size_t)dj * D0_ + DIN;
    float acc[8];
#pragma unroll
    for (int i = 0; i < 8; i++) acc[i] = 0.f;
    for (int k = 0; k < DBERT; k += 4) {
        float4 w4 = *(const float4*)&wrow[k];
#pragma unroll
        for (int i = 0; i < 8; i++) {
            int b = bq * 8 + i;
            float4 h4 = *(const float4*)&sh[b * 772 + k];
            acc[i] += w4.x * h4.x + w4.y * h4.y + w4.z * h4.z + w4.w * h4.w;
        }
    }
    float bias = b_ih0[dj] + b_hh0[dj];
#pragma unroll
    for (int i = 0; i < 8; i++)
        d_bertbias[(size_t)dj * 32 + bq * 8 + i] = acc[i] + bias;
}

// ---------------- GEMM: dst[m=dj][n=t*B+b] = A[m]·B[n] (+bias) ----------------
// 128x128 tile, 256 threads, double-buffered smem (A undup; dup in regs). 2 blocks/SM.
// WAIT=1: dst=d_preG1, mid-out n-order, acquire-spin on layer-0 counters (overlap lstm0).
#define GEMM_SMEM ((2 * 16 * 132 + 2 * 16 * 132) * 4)
template<int BT, int WAIT>
__global__ __launch_bounds__(256, 2) void gemm_kernel(
    const float* __restrict__ A, int lda, int K,
    const float* __restrict__ Bp, int ldb,
    int use_bb, const float* __restrict__ b1, const float* __restrict__ b2)
{
    extern __shared__ float sh[];
    float* AsBase = sh;                  // [2][16][132]
    float* WsBase = sh + 2 * 16 * 132;   // [2][16][132]
    const float* Bx = Bp ? Bp : (const float*)d_out0T;
    float* dstG = WAIT ? d_preG1 : d_preG;
    const int tid = threadIdx.x;

    int nt;
    if (WAIT) {
        int j = blockIdx.x >> 1;
        nt = (blockIdx.x & 1) ? (16 + j) : (15 - j);   // readiness (mid-out) order
        if (tid == 0) {
            unsigned tf = 64u * (unsigned)(4 * nt + 4);       // fwd: t<=4nt+3 done
            unsigned tb = 64u * (unsigned)(128 - 4 * nt);     // bwd: t>=4nt done
            while (ld_acq32(&d_bcnt[0][0]) < tf) __nanosleep(256);
            while (ld_acq32(&d_bcnt[1][0]) < tb) __nanosleep(256);
        }
        __syncthreads();
    } else {
        nt = blockIdx.x;
    }
    const int m0 = blockIdx.y * 128, n0 = nt * 128;

    const int am = tid >> 1, ak = (tid & 1) * 8;
    const int bk = tid >> 4, bn = (tid & 15) * 8;
    const int cn = tid >> 1, ck = (tid & 1) * 8;
    const int ty = tid >> 4, tx = tid & 15;

    ull acc[8][4];
#pragma unroll
    for (int i = 0; i < 8; i++)
#pragma unroll
        for (int j = 0; j < 4; j++) acc[i][j] = 0ull;

    float4 ra0, ra1, rb0, rb1;
    const int NT = K / 16;

    {
        const float* ap = &A[(size_t)(m0 + am) * lda + ak];
        ra0 = *(const float4*)ap; ra1 = *(const float4*)(ap + 4);
        if (BT) {
            const float* bp = &Bx[(size_t)bk * ldb + n0 + bn];
            rb0 = *(const float4*)bp; rb1 = *(const float4*)(bp + 4);
        } else {
            const float* bp = &Bx[(size_t)(n0 + cn) * ldb + ck];
            rb0 = *(const float4*)bp; rb1 = *(const float4*)(bp + 4);
        }
    }

    int p = 0;
    {
        float* As = AsBase;
        float* Ws = WsBase;
        float av[8] = {ra0.x, ra0.y, ra0.z, ra0.w, ra1.x, ra1.y, ra1.z, ra1.w};
#pragma unroll
        for (int i = 0; i < 8; i++) As[(ak + i) * 132 + am] = av[i];
        if (BT) {
            *(float4*)&Ws[bk * 132 + bn] = rb0;
            *(float4*)&Ws[bk * 132 + bn + 4] = rb1;
        } else {
            float bv[8] = {rb0.x, rb0.y, rb0.z, rb0.w, rb1.x, rb1.y, rb1.z, rb1.w};
#pragma unroll
            for (int i = 0; i < 8; i++) Ws[(ck + i) * 132 + cn] = bv[i];
        }
    }
    __syncthreads();

    for (int kt = 0; kt < NT; kt++) {
        if (kt + 1 < NT) {
            int k0 = (kt + 1) * 16;
            const float* ap = &A[(size_t)(m0 + am) * lda + k0 + ak];
            ra0 = *(const float4*)ap; ra1 = *(const float4*)(ap + 4);
            if (BT) {
                const float* bp = &Bx[(size_t)(k0 + bk) * ldb + n0 + bn];
                rb0 = *(const float4*)bp; rb1 = *(const float4*)(bp + 4);
            } else {
                const float* bp = &Bx[(size_t)(n0 + cn) * ldb + k0 + ck];
                rb0 = *(const float4*)bp; rb1 = *(const float4*)(bp + 4);
            }
        }
        {
            const float* As = AsBase + p * (16 * 132);
            const float* Ws = WsBase + p * (16 * 132);
#pragma unroll
            for (int kk = 0; kk < 16; kk++) {
                const float* ap = &As[kk * 132 + ty * 8];
                float4 f0 = *(const float4*)ap;
                float4 f1 = *(const float4*)(ap + 4);
                ull ax0 = packdup(f0.x), ax1 = packdup(f0.y);
                ull ax2 = packdup(f0.z), ax3 = packdup(f0.w);
                ull ax4 = packdup(f1.x), ax5 = packdup(f1.y);
                ull ax6 = packdup(f1.z), ax7 = packdup(f1.w);
                const float* wp = &Ws[kk * 132 + tx * 8];
                ulonglong2 w01 = *(const ulonglong2*)(wp);
                ulonglong2 w23 = *(const ulonglong2*)(wp + 4);
                fma2(acc[0][0], ax0, w01.x); fma2(acc[0][1], ax0, w01.y);
                fma2(acc[0][2], ax0, w23.x); fma2(acc[0][3], ax0, w23.y);
                fma2(acc[1][0], ax1, w01.x); fma2(acc[1][1], ax1, w01.y);
                fma2(acc[1][2], ax1, w23.x); fma2(acc[1][3], ax1, w23.y);
                fma2(acc[2][0], ax2, w01.x); fma2(acc[2][1], ax2, w01.y);
                fma2(acc[2][2], ax2, w23.x); fma2(acc[2][3], ax2, w23.y);
                fma2(acc[3][0], ax3, w01.x); fma2(acc[3][1], ax3, w01.y);
                fma2(acc[3][2], ax3, w23.x); fma2(acc[3][3], ax3, w23.y);
                fma2(acc[4][0], ax4, w01.x); fma2(acc[4][1], ax4, w01.y);
                fma2(acc[4][2], ax4, w23.x); fma2(acc[4][3], ax4, w23.y);
                fma2(acc[5][0], ax5, w01.x); fma2(acc[5][1], ax5, w01.y);
                fma2(acc[5][2], ax5, w23.x); fma2(acc[5][3], ax5, w23.y);
                fma2(acc[6][0], ax6, w01.x); fma2(acc[6][1], ax6, w01.y);
                fma2(acc[6][2], ax6, w23.x); fma2(acc[6][3], ax6, w23.y);
                fma2(acc[7][0], ax7, w01.x); fma2(acc[7][1], ax7, w01.y);
                fma2(acc[7][2], ax7, w23.x); fma2(acc[7][3], ax7, w23.y);
            }
        }
        if (kt + 1 < NT) {
            float* As = AsBase + (p ^ 1) * (16 * 132);
            float* Ws = WsBase + (p ^ 1) * (16 * 132);
            float av[8] = {ra0.x, ra0.y, ra0.z, ra0.w, ra1.x, ra1.y, ra1.z, ra1.w};
#pragma unroll
            for (int i = 0; i < 8; i++) As[(ak + i) * 132 + am] = av[i];
            if (BT) {
                *(float4*)&Ws[bk * 132 + bn] = rb0;
                *(float4*)&Ws[bk * 132 + bn + 4] = rb1;
            } else {
                float bv[8] = {rb0.x, rb0.y, rb0.z, rb0.w, rb1.x, rb1.y, rb1.z, rb1.w};
#pragma unroll
                for (int i = 0; i < 8; i++) Ws[(ck + i) * 132 + cn] = bv[i];
            }
        }
        __syncthreads();
        p ^= 1;
    }

#pragma unroll
    for (int i = 0; i < 8; i++) {
        int m = m0 + ty * 8 + i;
        float rowbias = use_bb ? 0.f : (b1[m] + b2[m]);
        float4 o0, o1;
        float2 v0 = unpackf2(acc[i][0]);
        float2 v1 = unpackf2(acc[i][1]);
        float2 v2 = unpackf2(acc[i][2]);
        float2 v3 = unpackf2(acc[i][3]);
        o0 = make_float4(v0.x, v0.y, v1.x, v1.y);
        o1 = make_float4(v2.x, v2.y, v3.x, v3.y);
        if (use_bb) {
            int bb = (tx * 8) & 31;
            float4 c0 = *(const float4*)&d_bertbias[(size_t)m * 32 + bb];
            float4 c1 = *(const float4*)&d_bertbias[(size_t)m * 32 + bb + 4];
            o0.x += c0.x; o0.y += c0.y; o0.z += c0.z; o0.w += c0.w;
            o1.x += c1.x; o1.y += c1.y; o1.z += c1.z; o1.w += c1.w;
        } else {
            o0.x += rowbias; o0.y += rowbias; o0.z += rowbias; o0.w += rowbias;
            o1.x += rowbias; o1.y += rowbias; o1.z += rowbias; o1.w += rowbias;
        }
        float* dst = &dstG[(size_t)m * 4096 + n0 + tx * 8];
        *(float4*)dst = o0;
        *(float4*)(dst + 4) = o1;
    }
}

// ---------------- persistent BiLSTM layer kernel (512 threads, 8-way k-split) ----------------
#define PSMEM ((512 * 32 + 512 * 32 + 8 * 32 * 33) * 4)
__global__ __launch_bounds__(512) void lstm_layer_kernel(
    const float* __restrict__ whh, int layer)
{
    extern __shared__ float sh[];
    float* wS  = sh;                         // [512][32] W rows, UNduplicated
    float* hT  = sh + 512 * 32;              // [512][32]
    float* red = sh + 512 * 32 + 512 * 32;   // [8][32][33]

    const int tid = threadIdx.x;
    const int d = blockIdx.x >> 6;
    const int hch = blockIdx.x & 63;
    const int hbase = hch * 8;
    const int bslot = layer * 2 + d;
    float* outT = layer ? d_out1T : d_out0T;
    const float* preG = layer ? d_preG1 : d_preG;

    // load 32 W_hh rows: wS[k*32 + c] = W[dj(c)][k]
    {
        int c = tid >> 4, kc = tid & 15;
        int g = c >> 3, hh = c & 7;
        const float* wrow = whh + ((size_t)d * 2048 + g * 512 + hbase + hh) * 512;
        for (int k = kc * 32; k < kc * 32 + 32; k += 4) {
            float4 v = *(const float4*)&wrow[k];
            wS[(k + 0) * 32 + c] = v.x;
            wS[(k + 1) * 32 + c] = v.y;
            wS[(k + 2) * 32 + c] = v.z;
            wS[(k + 3) * 32 + c] = v.w;
        }
    }
    __syncthreads();

    // allow PDL-dependent kernel (overlapped gemm) to begin launching
    pdl_launch_dependents();

    const int ks = tid >> 6, b8 = (tid >> 3) & 7, c8 = tid & 7;   // ks in [0,8)
    const int cu_hh = tid >> 5, cu_b = tid & 31;                  // valid tid<256
    float c_reg = 0.f;

    for (int ti = 0; ti < S_; ti++) {
        const int t = d ? (S_ - 1 - ti) : ti;

        // prefetch gate pre-activations (tid < 256; hidden under gate GEMM)
        float pg[4];
        if (tid < 256) {
#pragma unroll
            for (int gi = 0; gi < 4; gi++) {
                size_t dj = (size_t)d * 2048 + (size_t)gi * 512 + hbase + cu_hh;
                pg[gi] = __ldcg(&preG[dj * 4096 + t * 32 + cu_b]);
            }
        }

        if (ti > 0) {
            // ---- gate GEMM over k in [ks*64, ks*64+64), reg double-buffered ----
            ull acc[4][2];
#pragma unroll
            for (int i = 0; i < 4; i++) { acc[i][0] = 0ull; acc[i][1] = 0ull; }

            const float* wk = wS + c8 * 4 + ks * 64 * 32;
            const float* hk = hT + b8 * 4 + ks * 64 * 32;
            float4 nw = *(const float4*)wk;
            ulonglong2 nh = *(const ulonglong2*)hk;
            wk += 32; hk += 32;
#pragma unroll 4
            for (int k = 0; k < 63; k++) {
                float4 w4 = nw; ulonglong2 hv = nh;
                nw = *(const float4*)wk;
                nh = *(const ulonglong2*)hk;
                wk += 32; hk += 32;
                ull wx0 = packdup(w4.x);
                ull wx1 = packdup(w4.y);
                ull wx2 = packdup(w4.z);
                ull wx3 = packdup(w4.w);
                fma2(acc[0][0], hv.x, wx0); fma2(acc[0][1], hv.y, wx0);
                fma2(acc[1][0], hv.x, wx1); fma2(acc[1][1], hv.y, wx1);
                fma2(acc[2][0], hv.x, wx2); fma2(acc[2][1], hv.y, wx2);
                fma2(acc[3][0], hv.x, wx3); fma2(acc[3][1], hv.y, wx3);
            }
            {
                ull wx0 = packdup(nw.x);
                ull wx1 = packdup(nw.y);
                ull wx2 = packdup(nw.z);
                ull wx3 = packdup(nw.w);
                fma2(acc[0][0], nh.x, wx0); fma2(acc[0][1], nh.y, wx0);
                fma2(acc[1][0], nh.x, wx1); fma2(acc[1][1], nh.y, wx1);
                fma2(acc[2][0], nh.x, wx2); fma2(acc[2][1], nh.y, wx2);
                fma2(acc[3][0], nh.x, wx3); fma2(acc[3][1], nh.y, wx3);
            }

            // write partials: red[ks][b][c]
            {
                float* rp = red + ks * 1056 + (b8 * 4) * 33 + c8 * 4;
#pragma unroll
                for (int cc = 0; cc < 4; cc++) {
#pragma unroll
                    for (int bp = 0; bp < 2; bp++) {
                        float2 v = unpackf2(acc[cc][bp]);
                        rp[(2 * bp + 0) * 33 + cc] = v.x;
                        rp[(2 * bp + 1) * 33 + cc] = v.y;
                    }
                }
            }
            __syncthreads();
        }

        // ---- cell update: tid < 256, thread (cu_b, cu_hh) ----
        if (tid < 256) {
            float g[4];
#pragma unroll
            for (int gi = 0; gi < 4; gi++) {
                float s = pg[gi];
                if (ti > 0) {
                    int c = gi * 8 + cu_hh;
#pragma unroll
                    for (int kk = 0; kk < 8; kk++)
                        s += red[kk * 1056 + cu_b * 33 + c];
                }
                g[gi] = s;
            }
            float cn = fsig(g[1]) * c_reg + fsig(g[0]) * ftanh(g[2]);
            float hn = fsig(g[3]) * ftanh(cn);
            c_reg = cn;
            int hidx = hbase + cu_hh;
            d_hbuf[ti & 1][d][hidx][cu_b] = hn;
            outT[((size_t)(d * 512 + hidx)) * 4096 + t * 32 + cu_b] = hn;
        }

        // ---- per-direction grid barrier: monotonic arrival counter ----
        __syncthreads();
        if (tid == 0) {
            __threadfence();
            unsigned target = 64u * (unsigned)(ti + 1);
            unsigned old = atomicAdd((unsigned*)&d_bcnt[bslot][0], 1u);
            if (old + 1u < target) {
                while (d_bcnt[bslot][0] < target) { }
            }
            __threadfence();
        }
        __syncthreads();

        // ---- stage next h into SMEM (contiguous d_hbuf, 512 threads) ----
        if (ti < S_ - 1) {
            const float4* s4 = (const float4*)&d_hbuf[ti & 1][d][0][0];
            float4* d4 = (float4*)hT;
            for (int i = tid; i < 512 * 32 / 4; i += 512) d4[i] = __ldcg(&s4[i]);
            __syncthreads();
        }
    }
}

// ---------------- heads ----------------
__global__ __launch_bounds__(256) void head_kernel(
    const float* __restrict__ wp, const float* __restrict__ bp,
    const float* __restrict__ wm, const float* __restrict__ bm)
{
    __shared__ float Ash[32][65];
    __shared__ float Wsh[64][100];
    const int tid = threadIdx.x;
    const int row0 = blockIdx.x * 32;
    const int r = tid >> 3, jq = tid & 7;
    float acc[12];
#pragma unroll
    for (int j = 0; j < 12; j++) acc[j] = 0.f;

    const float* Xt = (const float*)d_out1T;
    for (int k0 = 0; k0 < 1024; k0 += 64) {
        for (int idx = tid; idx < 32 * 64; idx += 256) {
            int kk = idx >> 5, rr = idx & 31;
            Ash[rr][kk] = Xt[(size_t)(k0 + kk) * 4096 + row0 + rr];
        }
        for (int idx = tid; idx < 96 * 64; idx += 256) {
            int j = idx >> 6, kk = idx & 63;
            float v = (j < 32) ? wp[(size_t)j * 1024 + k0 + kk]
                               : wm[(size_t)(j - 32) * 1024 + k0 + kk];
            Wsh[kk][j] = v;
        }
        __syncthreads();
        for (int k = 0; k < 64; k++) {
            float a = Ash[r][k];
#pragma unroll
            for (int j = 0; j < 12; j++) acc[j] += a * Wsh[k][jq * 12 + j];
        }
        __syncthreads();
    }
#pragma unroll
    for (int j = 0; j < 12; j++) {
        int jj = jq * 12 + j;
        float bias = (jj < 32) ? bp[jj] : bm[jj - 32];
        d_feat[(size_t)(row0 + r) * 96 + jj] = acc[j] + bias;
    }
}

// ---------------- CRF ----------------
template <int K>
__global__ __launch_bounds__(128) void crf_kernel(
    int off, const int* __restrict__ labels,
    const float* __restrict__ start, const float* __restrict__ trans,
    const float* __restrict__ endv, float* __restrict__ out)
{
    __shared__ float tr[K * K];
    __shared__ float al[2][K];
    __shared__ float red[128];
    const int b = blockIdx.x, tid = threadIdx.x;

    for (int i = tid; i < K * K; i += 128) tr[i] = trans[i];

    float local = 0.f;
    for (int t = tid; t < S_; t += 128)
        local += d_feat[((size_t)t * Bz + b) * 96 + off + labels[t * Bz + b]];
    for (int t = tid; t < S_ - 1; t += 128)
        local += trans[labels[t * Bz + b] * K + labels[(t + 1) * Bz + b]];
    red[tid] = local;
    __syncthreads();
    for (int s = 64; s > 0; s >>= 1) {
        if (tid < s) red[tid] += red[tid + s];
        __syncthreads();
    }

    if (tid < K) al[0][tid] = start[tid] + d_feat[((size_t)0 * Bz + b) * 96 + off + tid];
    __syncthreads();
    int cur = 0;
    for (int t = 1; t < S_; t++) {
        if (tid < K) {
            float m = -1e30f;
#pragma unroll 4
            for (int i = 0; i < K; i++) {
                float v = al[cur][i] + tr[i * K + tid];
                m = fmaxf(m, v);
            }
            float s = 0.f;
#pragma unroll 4
            for (int i = 0; i < K; i++)
                s += __expf(al[cur][i] + tr[i * K + tid] - m);
            al[cur ^ 1][tid] = m + __logf(s) + d_feat[((size_t)t * Bz + b) * 96 + off + tid];
        }
        __syncthreads();
        cur ^= 1;
    }
    if (tid == 0) {
        float m = -1e30f;
        for (int j = 0; j < K; j++) m = fmaxf(m, al[cur][j] + endv[j]);
        float s = 0.f;
        for (int j = 0; j < K; j++) s += __expf(al[cur][j] + endv[j] - m);
        float den = m + __logf(s);
        float num = red[0] + start[labels[b]] + endv[labels[(S_ - 1) * Bz + b]];
        atomicAdd(out, -(num - den));
    }
}

// ---------------- launch ----------------
extern "C" void kernel_launch(void* const* d_in, const int* in_sizes, int n_in,
                              void* d_out, int out_size)
{
    const float* src  = (const float*)d_in[0];
    const float* bert = (const float*)d_in[1];
    const int*   labp = (const int*)d_in[2];
    const int*   labm = (const int*)d_in[3];
    const float* w_ih = (const float*)d_in[4];
    const float* w_hh = (const float*)d_in[5];
    const float* b_ih = (const float*)d_in[6];
    const float* b_hh = (const float*)d_in[7];
    const float* hwp  = (const float*)d_in[8];
    const float* hbp  = (const float*)d_in[9];
    const float* hwm  = (const float*)d_in[10];
    const float* hbm  = (const float*)d_in[11];
    const float* st_p = (const float*)d_in[12];
    const float* en_p = (const float*)d_in[13];
    const float* tr_p = (const float*)d_in[14];
    const float* st_m = (const float*)d_in[15];
    const float* en_m = (const float*)d_in[16];
    const float* tr_m = (const float*)d_in[17];
    float* out = (float*)d_out;

    cudaFuncSetAttribute(lstm_layer_kernel, cudaFuncAttributeMaxDynamicSharedMemorySize, PSMEM);
    cudaFuncSetAttribute(bert_bias_kernel, cudaFuncAttributeMaxDynamicSharedMemorySize, BB_SMEM);
    cudaFuncSetAttribute((const void*)gemm_kernel<0,0>, cudaFuncAttributeMaxDynamicSharedMemorySize, GEMM_SMEM);
    cudaFuncSetAttribute((const void*)gemm_kernel<1,1>, cudaFuncAttributeMaxDynamicSharedMemorySize, GEMM_SMEM);

    dim3 g128(32, 32);

    // 0: bert bias (also zeroes barrier counters + out)
    bert_bias_kernel<<<64, 256, BB_SMEM>>>(bert, w_ih, b_ih, b_hh, out);
    // 1: layer-0 input GEMM (K=256, bert folded into bias) -> d_preG
    gemm_kernel<0,0><<<g128, 256, GEMM_SMEM>>>(w_ih, 1024, 256, src, 256, 1, nullptr, nullptr);
    // 2: layer-0 BiLSTM (signals dependents after W-load)
    lstm_layer_kernel<<<128, 512, PSMEM>>>(w_hh, 0);
    // 3: layer-1 input GEMM -> d_preG1, PDL-overlapped with lstm0 (acquire-spin on counters)
    {
        cudaLaunchConfig_t cfg = {};
        cfg.gridDim = g128;
        cfg.blockDim = dim3(256, 1, 1);
        cfg.dynamicSmemBytes = GEMM_SMEM;
        cfg.stream = 0;
        cudaLaunchAttribute attr[1];
        attr[0].id = cudaLaunchAttributeProgrammaticStreamSerialization;
        attr[0].val.programmaticStreamSerializationAllowed = 1;
        cfg.attrs = attr;
        cfg.numAttrs = 1;
        cudaError_t e = cudaLaunchKernelEx(&cfg, gemm_kernel<1,1>,
            (const float*)(w_ih + (size_t)4096 * 1024), 1024, 1024,
            (const float*)nullptr, 4096, 0,
            (const float*)(b_ih + 4096), (const float*)(b_hh + 4096));
        if (e != cudaSuccess) {
            cudaGetLastError();
            gemm_kernel<1,1><<<g128, 256, GEMM_SMEM>>>(w_ih + (size_t)4096 * 1024, 1024, 1024,
                                                       nullptr, 4096, 0, b_ih + 4096, b_hh + 4096);
        }
    }
    // 4: layer-1 BiLSTM
    lstm_layer_kernel<<<128, 512, PSMEM>>>(w_hh + (size_t)2 * 2048 * 512, 1);
    // 5-7: heads + CRFs (plain stream order)
    head_kernel<<<128, 256>>>(hwp, hbp, hwm, hbm);
    crf_kernel<NTP><<<32, 128>>>(0, labp, st_p, tr_p, en_p, out);
    crf_kernel<NTM><<<32, 128>>>(32, labm, st_m, tr_m, en_m, out);
}